// round 15
// baseline (speedup 1.0000x reference)
#include <cuda_runtime.h>
#include <cuda_bf16.h>
#include <cstdint>

// ---------------- problem constants ----------------
#define B_ROWS 1024
#define D_DIM  512
#define C_CLS  100000
#define S_SCALE 64.0f
#define M_MARG  0.5f
#define EPS_A   1e-07f

// fp8 quantization scales
#define SX 16.0f
#define SW 64.0f
#define INV_SXSW (S_SCALE / (SX * SW))                 // 0.0625
#define EXP2K (INV_SXSW * 1.4426950408889634f)         // ex2(acc*EXP2K)

// GEMM tiling: stripe = 128 classes; unit = (stripe, row-tile of 128 rows)
#define BM 128
#define BN 128
#define BK 128
#define ROW_BYTES   144                        // 128 fp8 = 128B data + 16B pad
#define TILE_BYTES  (128 * ROW_BYTES)          // 18432
#define STAGE_BYTES (2 * TILE_BYTES)           // X + W
#define SMEM_BYTES  (2 * STAGE_BYTES + 256)

#define NSTRIPE 782                            // ceil(100000/128)
#define NRT     8                              // row-tiles (1024/128)
#define NUNITS  (NSTRIPE * NRT)                // 6256
#define GRID    304                            // 152 SMs x 2 CTAs -> exactly 1 wave

// ---------------- scratch ----------------
__device__ float    g_xn[B_ROWS * D_DIM];
__device__ uint8_t  g_x8[B_ROWS * D_DIM];
__device__ uint8_t  g_w8[(size_t)C_CLS * D_DIM];
__device__ float    g_rowsum[B_ROWS];
__device__ float    g_tgt[B_ROWS];
__device__ int      g_y_is64;

// ---------------- helpers ----------------
__device__ __forceinline__ void ldsm_x4(unsigned r[4], unsigned addr) {
    asm volatile("ldmatrix.sync.aligned.m8n8.x4.shared.b16 {%0,%1,%2,%3}, [%4];"
                 : "=r"(r[0]), "=r"(r[1]), "=r"(r[2]), "=r"(r[3]) : "r"(addr));
}

__device__ __forceinline__ void mma_fp8(float c[4], const unsigned a[4], const unsigned b[2]) {
    asm volatile(
        "mma.sync.aligned.m16n8k32.row.col.f32.e4m3.e4m3.f32 "
        "{%0,%1,%2,%3},{%4,%5,%6,%7},{%8,%9},{%0,%1,%2,%3};"
        : "+f"(c[0]), "+f"(c[1]), "+f"(c[2]), "+f"(c[3])
        : "r"(a[0]), "r"(a[1]), "r"(a[2]), "r"(a[3]),
          "r"(b[0]), "r"(b[1]));
}

__device__ __forceinline__ float ex2f(float x) {
    float y;
    asm("ex2.approx.ftz.f32 %0, %1;" : "=f"(y) : "f"(x));
    return y;
}

__device__ __forceinline__ unsigned pack_e4m3x4(float x0, float x1, float x2, float x3) {
    unsigned short lo, hi;
    asm("cvt.rn.satfinite.e4m3x2.f32 %0, %1, %2;" : "=h"(lo) : "f"(x1), "f"(x0));
    asm("cvt.rn.satfinite.e4m3x2.f32 %0, %1, %2;" : "=h"(hi) : "f"(x3), "f"(x2));
    return (unsigned)lo | ((unsigned)hi << 16);
}

__device__ __forceinline__ void cp16(unsigned dst, const void* src, bool valid) {
    int sz = valid ? 16 : 0;
    asm volatile("cp.async.cg.shared.global [%0], [%1], 16, %2;\n"
                 :: "r"(dst), "l"(src), "r"(sz));
}
__device__ __forceinline__ void cp_commit() {
    asm volatile("cp.async.commit_group;\n" ::: "memory");
}
__device__ __forceinline__ void cp_wait0() {
    asm volatile("cp.async.wait_group 0;\n" ::: "memory");
}

// ---------------- kernel 0: detect y_true dtype ----------------
__global__ void detect_kernel(const int* __restrict__ y32) {
    int all_zero = 1;
    #pragma unroll
    for (int i = 0; i < 16; i++)
        if (y32[2 * i + 1] != 0) all_zero = 0;
    g_y_is64 = all_zero;
}

// ---------------- kernel 1: L2-normalize + quantize + fp32 true-class logit ----------------
__global__ __launch_bounds__(128) void norm_tgt_kernel(const float* __restrict__ X,
                                                       const float* __restrict__ W,
                                                       const void* __restrict__ y) {
    int b = blockIdx.x;
    const float* xr = X + (size_t)b * D_DIM;
    float s = 0.f;
    #pragma unroll
    for (int i = threadIdx.x; i < D_DIM; i += 128) {
        float v = xr[i];
        s += v * v;
    }
    #pragma unroll
    for (int o = 16; o > 0; o >>= 1) s += __shfl_xor_sync(0xffffffffu, s, o);
    __shared__ float red[4];
    int w = threadIdx.x >> 5;
    if ((threadIdx.x & 31) == 0) red[w] = s;
    __syncthreads();
    float tot = red[0] + red[1] + red[2] + red[3];
    float inv = 1.0f / fmaxf(sqrtf(tot), 1e-12f);

    int j = threadIdx.x * 4;
    float4 v = *(const float4*)(xr + j);
    v.x *= inv; v.y *= inv; v.z *= inv; v.w *= inv;
    *(float4*)(g_xn + (size_t)b * D_DIM + j) = v;
    unsigned p = pack_e4m3x4(v.x * SX, v.y * SX, v.z * SX, v.w * SX);
    *(unsigned*)(g_x8 + (size_t)b * D_DIM + j) = p;

    long long c;
    if (g_y_is64) c = ((const long long*)y)[b];
    else          c = (long long)((const int*)y)[b];
    if (c < 0) c = 0;
    if (c >= C_CLS) c = C_CLS - 1;
    float4 wv = *(const float4*)(W + (size_t)c * D_DIM + j);
    float t = v.x * wv.x + v.y * wv.y + v.z * wv.z + v.w * wv.w;
    #pragma unroll
    for (int o = 16; o > 0; o >>= 1) t += __shfl_xor_sync(0xffffffffu, t, o);
    __syncthreads();
    if ((threadIdx.x & 31) == 0) red[w] = t;
    __syncthreads();
    if (threadIdx.x == 0) {
        g_tgt[b] = red[0] + red[1] + red[2] + red[3];
        g_rowsum[b] = 0.f;
    }
}

// ---------------- kernel 2: balanced-range fused W-quantize + fp8 GEMM + exp + row-sum ----
// 304 CTAs (1 wave at occ=2), each owns a contiguous range of (stripe,row-tile)
// units out of 6256 — removes the 14% wave-quantization tail of the 782-CTA grid.
// Mainloop geometry frozen from R11.
__global__ __launch_bounds__(256, 2) void gemm_exp_kernel(const float* __restrict__ W) {
    extern __shared__ char sm_raw[];

    const int tid  = threadIdx.x;
    const int lane = tid & 31;
    const int warp = tid >> 5;
    const int warpM = warp & 1;    // 2 warps over M (64 rows each)
    const int warpN = warp >> 1;   // 4 warps over N (32 cols each)

    // unit range for this CTA (stripe-major: unit = stripe*8 + rowtile)
    const int u0 = (int)(((long long)blockIdx.x * NUNITS) / GRID);
    const int u1 = (int)(((long long)(blockIdx.x + 1) * NUNITS) / GRID);

    unsigned sbase = (unsigned)__cvta_generic_to_shared(sm_raw);
    sbase = (sbase + 255u) & ~255u;

    const int lr  = tid >> 3;      // load row 0..31
    const int seg = tid & 7;       // 16B segment

    unsigned st_off[4];
    #pragma unroll
    for (int i = 0; i < 4; i++)
        st_off[i] = (unsigned)((lr + 32 * i) * ROW_BYTES + seg * 16);

    const int lrow = lane & 15;
    const int lhi  = (lane >> 4) * 16;
    const int qrow = lane >> 2;
    const int qcol = lane & 3;

    unsigned a_off[4], b_off[2];
    #pragma unroll
    for (int mi = 0; mi < 4; mi++)
        a_off[mi] = (unsigned)((warpM * 64 + mi * 16 + lrow) * ROW_BYTES + lhi);
    #pragma unroll
    for (int p = 0; p < 2; p++)
        b_off[p] = (unsigned)((warpN * 32 + p * 16 + lrow) * ROW_BYTES + lhi) + (unsigned)TILE_BYTES;

    float acc[4][4][4];
    #pragma unroll
    for (int mi = 0; mi < 4; mi++)
        #pragma unroll
        for (int ni = 0; ni < 4; ni++)
            #pragma unroll
            for (int r = 0; r < 4; r++) acc[mi][ni][r] = 0.f;

    int u = u0;
    while (u < u1) {
        const int stripe = u / NRT;
        const int r0 = u - stripe * NRT;
        int r1 = r0 + (u1 - u);
        if (r1 > NRT) r1 = NRT;
        u += (r1 - r0);

        const int colbase = stripe * BN;
        const bool full_tile = (colbase + BN <= C_CLS);

        // ---- quantize this stripe of W to e4m3 (duplicate writes at range
        //      boundaries are byte-identical -> benign) ----
        {
            const size_t base = (size_t)colbase * D_DIM;
            const int vrows = full_tile ? BN : (C_CLS - colbase);
            const size_t velems = (size_t)vrows * D_DIM;
            for (size_t i = (size_t)tid * 4; i < velems; i += 256 * 4) {
                float4 v = *(const float4*)(W + base + i);
                unsigned p = pack_e4m3x4(v.x * SW, v.y * SW, v.z * SW, v.w * SW);
                *(unsigned*)(g_w8 + base + i) = p;
            }
            __syncthreads();
        }

        // W row pointers for this stripe
        bool wvalid[4];
        const uint8_t* wrow[4];
        #pragma unroll
        for (int i = 0; i < 4; i++) {
            int c = colbase + lr + 32 * i;
            wvalid[i] = (c < C_CLS);
            wrow[i] = g_w8 + (size_t)(wvalid[i] ? c : colbase) * D_DIM + seg * 16;
        }

        auto load_chunk = [&](int rt, int kt, int st) {
            const unsigned xs = sbase + (unsigned)st * (unsigned)STAGE_BYTES;
            const unsigned ws = xs + (unsigned)TILE_BYTES;
            const uint8_t* xb = g_x8 + (size_t)(rt * BM) * D_DIM + kt * BK + seg * 16;
            #pragma unroll
            for (int i = 0; i < 4; i++) {
                cp16(xs + st_off[i], xb + (size_t)(lr + 32 * i) * D_DIM, true);
                cp16(ws + st_off[i], wrow[i] + kt * BK, wvalid[i]);
            }
        };

        // pipeline prologue for this stripe segment
        load_chunk(r0, 0, 0);
        cp_commit();

        for (int rt = r0; rt < r1; rt++) {
            #pragma unroll
            for (int kt = 0; kt < 4; kt++) {
                const int s = kt & 1;   // (rt-r0)*4 even -> stage compile-time per kt

                cp_wait0();
                __syncthreads();

                if (kt < 3) {
                    load_chunk(rt, kt + 1, s ^ 1);
                    cp_commit();
                } else if (rt + 1 < r1) {
                    load_chunk(rt + 1, 0, s ^ 1);
                    cp_commit();
                }

                const unsigned stg = sbase + (unsigned)(s * STAGE_BYTES);

                #pragma unroll
                for (int ks = 0; ks < 4; ks++) {
                    const unsigned kb = stg + (unsigned)(ks * 32);
                    unsigned a[4][4];
                    unsigned bq[2][4];
                    #pragma unroll
                    for (int mi = 0; mi < 4; mi++)
                        ldsm_x4(a[mi], kb + a_off[mi]);
                    #pragma unroll
                    for (int p = 0; p < 2; p++)
                        ldsm_x4(bq[p], kb + b_off[p]);
                    #pragma unroll
                    for (int mi = 0; mi < 4; mi++) {
                        #pragma unroll
                        for (int p = 0; p < 2; p++) {
                            unsigned b0[2] = { bq[p][0], bq[p][2] };
                            unsigned b1[2] = { bq[p][1], bq[p][3] };
                            mma_fp8(acc[mi][2 * p + 0], a[mi], b0);
                            mma_fp8(acc[mi][2 * p + 1], a[mi], b1);
                        }
                    }
                }
            }

            // epilogue for this row-tile
            if (full_tile) {
                #pragma unroll
                for (int mi = 0; mi < 4; mi++) {
                    int row0 = rt * BM + warpM * 64 + mi * 16 + qrow;
                    int row1 = row0 + 8;
                    float s0 = 0.f, s1 = 0.f;
                    #pragma unroll
                    for (int ni = 0; ni < 4; ni++) {
                        s0 += ex2f(EXP2K * acc[mi][ni][0]);
                        s0 += ex2f(EXP2K * acc[mi][ni][1]);
                        s1 += ex2f(EXP2K * acc[mi][ni][2]);
                        s1 += ex2f(EXP2K * acc[mi][ni][3]);
                        #pragma unroll
                        for (int r = 0; r < 4; r++) acc[mi][ni][r] = 0.f;
                    }
                    s0 += __shfl_xor_sync(0xffffffffu, s0, 1);
                    s0 += __shfl_xor_sync(0xffffffffu, s0, 2);
                    s1 += __shfl_xor_sync(0xffffffffu, s1, 1);
                    s1 += __shfl_xor_sync(0xffffffffu, s1, 2);
                    if (qcol == 0) {
                        atomicAdd(g_rowsum + row0, s0);
                        atomicAdd(g_rowsum + row1, s1);
                    }
                }
            } else {
                #pragma unroll
                for (int mi = 0; mi < 4; mi++) {
                    int row0 = rt * BM + warpM * 64 + mi * 16 + qrow;
                    int row1 = row0 + 8;
                    float s0 = 0.f, s1 = 0.f;
                    #pragma unroll
                    for (int ni = 0; ni < 4; ni++) {
                        int c0 = colbase + warpN * 32 + ni * 8 + 2 * qcol;
                        int c1 = c0 + 1;
                        if (c0 < C_CLS) {
                            s0 += ex2f(EXP2K * acc[mi][ni][0]);
                            s1 += ex2f(EXP2K * acc[mi][ni][2]);
                        }
                        if (c1 < C_CLS) {
                            s0 += ex2f(EXP2K * acc[mi][ni][1]);
                            s1 += ex2f(EXP2K * acc[mi][ni][3]);
                        }
                        #pragma unroll
                        for (int r = 0; r < 4; r++) acc[mi][ni][r] = 0.f;
                    }
                    s0 += __shfl_xor_sync(0xffffffffu, s0, 1);
                    s0 += __shfl_xor_sync(0xffffffffu, s0, 2);
                    s1 += __shfl_xor_sync(0xffffffffu, s1, 1);
                    s1 += __shfl_xor_sync(0xffffffffu, s1, 2);
                    if (qcol == 0) {
                        atomicAdd(g_rowsum + row0, s0);
                        atomicAdd(g_rowsum + row1, s1);
                    }
                }
            }
        }
        // drain pipeline before next stripe (its W may not be quantized yet)
        cp_wait0();
        __syncthreads();
    }
}

// ---------------- kernel 3: per-row loss + mean ----------------
__global__ __launch_bounds__(1024) void loss_kernel(float* __restrict__ out) {
    int b = threadIdx.x;
    float t = g_tgt[b];
    float tc = fminf(fmaxf(t, -1.0f + EPS_A), 1.0f - EPS_A);
    float num = S_SCALE * cosf(acosf(tc) + M_MARG);
    float excl = g_rowsum[b] - expf(S_SCALE * t);
    float denom = expf(num) + excl;
    float L = num - logf(denom);

    #pragma unroll
    for (int o = 16; o > 0; o >>= 1) L += __shfl_xor_sync(0xffffffffu, L, o);
    __shared__ float red[32];
    int w = threadIdx.x >> 5;
    if ((threadIdx.x & 31) == 0) red[w] = L;
    __syncthreads();
    if (w == 0) {
        float v = red[threadIdx.x & 31];
        #pragma unroll
        for (int o = 16; o > 0; o >>= 1) v += __shfl_xor_sync(0xffffffffu, v, o);
        if (threadIdx.x == 0) out[0] = -v / (float)B_ROWS;
    }
}

// ---------------- launch ----------------
extern "C" void kernel_launch(void* const* d_in, const int* in_sizes, int n_in,
                              void* d_out, int out_size) {
    const float* features = (const float*)d_in[0];
    const float* W        = (const float*)d_in[1];
    const void*  y_true   = d_in[2];
    float* out = (float*)d_out;

    cudaFuncSetAttribute(gemm_exp_kernel,
                         cudaFuncAttributeMaxDynamicSharedMemorySize, SMEM_BYTES);

    detect_kernel<<<1, 1>>>((const int*)y_true);
    norm_tgt_kernel<<<B_ROWS, 128>>>(features, W, y_true);
    gemm_exp_kernel<<<GRID, 256, SMEM_BYTES>>>(W);
    loss_kernel<<<1, 1024>>>(out);
}

// round 16
// speedup vs baseline: 1.2028x; 1.2028x over previous
#include <cuda_runtime.h>
#include <cuda_bf16.h>
#include <cstdint>

// ---------------- problem constants ----------------
#define B_ROWS 1024
#define D_DIM  512
#define C_CLS  100000
#define S_SCALE 64.0f
#define M_MARG  0.5f
#define EPS_A   1e-07f

// fp8 quantization scales: logits come out multiplied by SX*SW = 1024
#define SX 16.0f
#define SW 64.0f
#define INV_SXSW (S_SCALE / (SX * SW))                 // 0.0625
#define EXP2K (INV_SXSW * 1.4426950408889634f)         // ex2(acc*EXP2K)

// GEMM tiling: per-CTA 128 rows x 128 classes, K chunked by 128 fp8 elems
#define BM 128
#define BN 128
#define BK 128
#define ROW_BYTES   144                        // 128 fp8 = 128B data + 16B pad
#define TILE_BYTES  (128 * ROW_BYTES)          // 18432
#define STAGE_BYTES (2 * TILE_BYTES)           // X + W
#define SMEM_BYTES  (2 * STAGE_BYTES + 256)
#define GRID_C 782                             // ceil(100000/128)

// ---------------- scratch ----------------
__device__ float    g_xn[B_ROWS * D_DIM];          // normalized features fp32
__device__ uint8_t  g_x8[B_ROWS * D_DIM];          // normalized features e4m3 (x SX)
__device__ uint8_t  g_w8[(size_t)C_CLS * D_DIM];   // W e4m3 (x SW), written by gemm prologue
__device__ float    g_rowsum[B_ROWS];
__device__ float    g_tgt[B_ROWS];
__device__ unsigned g_done;                        // gemm completion counter (reset each call)

// ---------------- helpers ----------------
__device__ __forceinline__ void ldsm_x4(unsigned r[4], unsigned addr) {
    asm volatile("ldmatrix.sync.aligned.m8n8.x4.shared.b16 {%0,%1,%2,%3}, [%4];"
                 : "=r"(r[0]), "=r"(r[1]), "=r"(r[2]), "=r"(r[3]) : "r"(addr));
}

__device__ __forceinline__ void mma_fp8(float c[4], const unsigned a[4], const unsigned b[2]) {
    asm volatile(
        "mma.sync.aligned.m16n8k32.row.col.f32.e4m3.e4m3.f32 "
        "{%0,%1,%2,%3},{%4,%5,%6,%7},{%8,%9},{%0,%1,%2,%3};"
        : "+f"(c[0]), "+f"(c[1]), "+f"(c[2]), "+f"(c[3])
        : "r"(a[0]), "r"(a[1]), "r"(a[2]), "r"(a[3]),
          "r"(b[0]), "r"(b[1]));
}

__device__ __forceinline__ float ex2f(float x) {
    float y;
    asm("ex2.approx.ftz.f32 %0, %1;" : "=f"(y) : "f"(x));
    return y;
}

// pack 4 floats -> 4 e4m3 bytes (byte i = element i)
__device__ __forceinline__ unsigned pack_e4m3x4(float x0, float x1, float x2, float x3) {
    unsigned short lo, hi;
    asm("cvt.rn.satfinite.e4m3x2.f32 %0, %1, %2;" : "=h"(lo) : "f"(x1), "f"(x0));
    asm("cvt.rn.satfinite.e4m3x2.f32 %0, %1, %2;" : "=h"(hi) : "f"(x3), "f"(x2));
    return (unsigned)lo | ((unsigned)hi << 16);
}

__device__ __forceinline__ void cp16(unsigned dst, const void* src, bool valid) {
    int sz = valid ? 16 : 0;
    asm volatile("cp.async.cg.shared.global [%0], [%1], 16, %2;\n"
                 :: "r"(dst), "l"(src), "r"(sz));
}
__device__ __forceinline__ void cp_commit() {
    asm volatile("cp.async.commit_group;\n" ::: "memory");
}
__device__ __forceinline__ void cp_wait0() {
    asm volatile("cp.async.wait_group 0;\n" ::: "memory");
}

// ---------------- kernel 1: L2-normalize + quantize + fp32 true-class logit ----------------
// Also: per-block inline y-dtype detection (16 cached loads, uniform) and
// g_done reset (block 0) for the gemm's fused-loss completion counter.
__global__ __launch_bounds__(128) void norm_tgt_kernel(const float* __restrict__ X,
                                                       const float* __restrict__ W,
                                                       const void* __restrict__ y) {
    int b = blockIdx.x;
    if (b == 0 && threadIdx.x == 0) g_done = 0;

    const float* xr = X + (size_t)b * D_DIM;
    float s = 0.f;
    #pragma unroll
    for (int i = threadIdx.x; i < D_DIM; i += 128) {
        float v = xr[i];
        s += v * v;
    }
    #pragma unroll
    for (int o = 16; o > 0; o >>= 1) s += __shfl_xor_sync(0xffffffffu, s, o);
    __shared__ float red[4];
    int w = threadIdx.x >> 5;
    if ((threadIdx.x & 31) == 0) red[w] = s;
    __syncthreads();
    float tot = red[0] + red[1] + red[2] + red[3];
    float inv = 1.0f / fmaxf(sqrtf(tot), 1e-12f);

    int j = threadIdx.x * 4;
    float4 v = *(const float4*)(xr + j);
    v.x *= inv; v.y *= inv; v.z *= inv; v.w *= inv;
    *(float4*)(g_xn + (size_t)b * D_DIM + j) = v;
    unsigned p = pack_e4m3x4(v.x * SX, v.y * SX, v.z * SX, v.w * SX);
    *(unsigned*)(g_x8 + (size_t)b * D_DIM + j) = p;

    // inline y dtype detection: int64 values < 2^31 -> all odd 32-bit words zero
    const int* y32 = (const int*)y;
    int is64 = 1;
    #pragma unroll
    for (int i = 0; i < 16; i++)
        if (y32[2 * i + 1] != 0) is64 = 0;

    long long c;
    if (is64) c = ((const long long*)y)[b];
    else      c = (long long)y32[b];
    if (c < 0) c = 0;
    if (c >= C_CLS) c = C_CLS - 1;
    float4 wv = *(const float4*)(W + (size_t)c * D_DIM + j);
    float t = v.x * wv.x + v.y * wv.y + v.z * wv.z + v.w * wv.w;
    #pragma unroll
    for (int o = 16; o > 0; o >>= 1) t += __shfl_xor_sync(0xffffffffu, t, o);
    __syncthreads();
    if ((threadIdx.x & 31) == 0) red[w] = t;
    __syncthreads();
    if (threadIdx.x == 0) {
        g_tgt[b] = red[0] + red[1] + red[2] + red[3];
        g_rowsum[b] = 0.f;
    }
}

// ---------------- kernel 2: fused W-quantize + fp8 GEMM + exp + row-sum + final loss ----
// R13 geometry frozen: 256 threads, 8 warps (2M x 4N, per-warp 64x32),
// 2-stage cp.async, occ=2, A-fragment double buffer.
// NEW: last-CTA-out computes the final scalar loss (threadfence reduction).
__global__ __launch_bounds__(256, 2) void gemm_exp_kernel(const float* __restrict__ W,
                                                          float* __restrict__ out) {
    extern __shared__ char sm_raw[];

    const int tid  = threadIdx.x;
    const int lane = tid & 31;
    const int warp = tid >> 5;
    const int warpM = warp & 1;    // 2 warps over M (64 rows each)
    const int warpN = warp >> 1;   // 4 warps over N (32 cols each)
    const int colbase = blockIdx.x * BN;
    const bool full_tile = (colbase + BN <= C_CLS);

    // ---- prologue: quantize this CTA's W stripe to e4m3 (x SW) ----
    {
        const size_t base = (size_t)colbase * D_DIM;
        const int vrows = full_tile ? BN : (C_CLS - colbase);
        const size_t velems = (size_t)vrows * D_DIM;
        for (size_t i = (size_t)tid * 4; i < velems; i += 256 * 4) {
            float4 v = *(const float4*)(W + base + i);
            unsigned p = pack_e4m3x4(v.x * SW, v.y * SW, v.z * SW, v.w * SW);
            *(unsigned*)(g_w8 + base + i) = p;
        }
        __syncthreads();
    }

    unsigned sbase = (unsigned)__cvta_generic_to_shared(sm_raw);
    sbase = (sbase + 255u) & ~255u;

    const int lr  = tid >> 3;      // load row 0..31
    const int seg = tid & 7;       // 16B segment (8 per 128B row)

    bool wvalid[4];
    const uint8_t* wrow[4];
    #pragma unroll
    for (int i = 0; i < 4; i++) {
        int c = colbase + lr + 32 * i;
        wvalid[i] = (c < C_CLS);
        wrow[i] = g_w8 + (size_t)(wvalid[i] ? c : colbase) * D_DIM + seg * 16;
    }

    unsigned st_off[4];
    #pragma unroll
    for (int i = 0; i < 4; i++)
        st_off[i] = (unsigned)((lr + 32 * i) * ROW_BYTES + seg * 16);

    auto load_chunk = [&](int rt, int kt, int st) {
        const unsigned xs = sbase + (unsigned)st * (unsigned)STAGE_BYTES;
        const unsigned ws = xs + (unsigned)TILE_BYTES;
        const uint8_t* xb = g_x8 + (size_t)(rt * BM) * D_DIM + kt * BK + seg * 16;
        #pragma unroll
        for (int i = 0; i < 4; i++) {
            cp16(xs + st_off[i], xb + (size_t)(lr + 32 * i) * D_DIM, true);
            cp16(ws + st_off[i], wrow[i] + kt * BK, wvalid[i]);
        }
    };

    const int lrow = lane & 15;
    const int lhi  = (lane >> 4) * 16;
    const int qrow = lane >> 2;
    const int qcol = lane & 3;

    unsigned a_off[4], b_off[2];
    #pragma unroll
    for (int mi = 0; mi < 4; mi++)
        a_off[mi] = (unsigned)((warpM * 64 + mi * 16 + lrow) * ROW_BYTES + lhi);
    #pragma unroll
    for (int p = 0; p < 2; p++)
        b_off[p] = (unsigned)((warpN * 32 + p * 16 + lrow) * ROW_BYTES + lhi) + (unsigned)TILE_BYTES;

    load_chunk(0, 0, 0);
    cp_commit();

    float acc[4][4][4];
    #pragma unroll
    for (int mi = 0; mi < 4; mi++)
        #pragma unroll
        for (int ni = 0; ni < 4; ni++)
            #pragma unroll
            for (int r = 0; r < 4; r++) acc[mi][ni][r] = 0.f;

    for (int rt = 0; rt < 8; rt++) {
        #pragma unroll
        for (int kt = 0; kt < 4; kt++) {
            const int s = kt & 1;

            cp_wait0();
            __syncthreads();

            // prefetch next chunk
            if (kt < 3) {
                load_chunk(rt, kt + 1, s ^ 1);
                cp_commit();
            } else if (rt < 7) {
                load_chunk(rt + 1, 0, s ^ 1);
                cp_commit();
            }

            const unsigned stg = sbase + (unsigned)(s * STAGE_BYTES);

            // A-fragment double buffer across k-steps (B loaded per k-step, first)
            unsigned a[2][4][4];
            #pragma unroll
            for (int mi = 0; mi < 4; mi++)
                ldsm_x4(a[0][mi], stg + a_off[mi]);   // preload A for ks=0

            #pragma unroll
            for (int ks = 0; ks < 4; ks++) {
                const int cur = ks & 1;
                const int nxt = cur ^ 1;
                const unsigned kb = stg + (unsigned)(ks * 32);

                unsigned bq[2][4];
                #pragma unroll
                for (int p = 0; p < 2; p++)
                    ldsm_x4(bq[p], kb + b_off[p]);

                if (ks < 3) {
                    const unsigned kb2 = stg + (unsigned)((ks + 1) * 32);
                    #pragma unroll
                    for (int mi = 0; mi < 4; mi++)
                        ldsm_x4(a[nxt][mi], kb2 + a_off[mi]);
                }

                #pragma unroll
                for (int mi = 0; mi < 4; mi++) {
                    #pragma unroll
                    for (int p = 0; p < 2; p++) {
                        unsigned b0[2] = { bq[p][0], bq[p][2] };
                        unsigned b1[2] = { bq[p][1], bq[p][3] };
                        mma_fp8(acc[mi][2 * p + 0], a[cur][mi], b0);
                        mma_fp8(acc[mi][2 * p + 1], a[cur][mi], b1);
                    }
                }
            }
        }

        // epilogue for this row-tile
        if (full_tile) {
            #pragma unroll
            for (int mi = 0; mi < 4; mi++) {
                int r0 = rt * BM + warpM * 64 + mi * 16 + qrow;
                int r1 = r0 + 8;
                float s0 = 0.f, s1 = 0.f;
                #pragma unroll
                for (int ni = 0; ni < 4; ni++) {
                    s0 += ex2f(EXP2K * acc[mi][ni][0]);
                    s0 += ex2f(EXP2K * acc[mi][ni][1]);
                    s1 += ex2f(EXP2K * acc[mi][ni][2]);
                    s1 += ex2f(EXP2K * acc[mi][ni][3]);
                    #pragma unroll
                    for (int r = 0; r < 4; r++) acc[mi][ni][r] = 0.f;
                }
                s0 += __shfl_xor_sync(0xffffffffu, s0, 1);
                s0 += __shfl_xor_sync(0xffffffffu, s0, 2);
                s1 += __shfl_xor_sync(0xffffffffu, s1, 1);
                s1 += __shfl_xor_sync(0xffffffffu, s1, 2);
                if (qcol == 0) {
                    atomicAdd(g_rowsum + r0, s0);
                    atomicAdd(g_rowsum + r1, s1);
                }
            }
        } else {
            #pragma unroll
            for (int mi = 0; mi < 4; mi++) {
                int r0 = rt * BM + warpM * 64 + mi * 16 + qrow;
                int r1 = r0 + 8;
                float s0 = 0.f, s1 = 0.f;
                #pragma unroll
                for (int ni = 0; ni < 4; ni++) {
                    int c0 = colbase + warpN * 32 + ni * 8 + 2 * qcol;
                    int c1 = c0 + 1;
                    if (c0 < C_CLS) {
                        s0 += ex2f(EXP2K * acc[mi][ni][0]);
                        s1 += ex2f(EXP2K * acc[mi][ni][2]);
                    }
                    if (c1 < C_CLS) {
                        s0 += ex2f(EXP2K * acc[mi][ni][1]);
                        s1 += ex2f(EXP2K * acc[mi][ni][3]);
                    }
                    #pragma unroll
                    for (int r = 0; r < 4; r++) acc[mi][ni][r] = 0.f;
                }
                s0 += __shfl_xor_sync(0xffffffffu, s0, 1);
                s0 += __shfl_xor_sync(0xffffffffu, s0, 2);
                s1 += __shfl_xor_sync(0xffffffffu, s1, 1);
                s1 += __shfl_xor_sync(0xffffffffu, s1, 2);
                if (qcol == 0) {
                    atomicAdd(g_rowsum + r0, s0);
                    atomicAdd(g_rowsum + r1, s1);
                }
            }
        }
    }

    // ---- fused final loss: last CTA out computes the scalar (threadfence reduction) ----
    __syncthreads();
    __threadfence();
    __shared__ unsigned s_rank;
    if (tid == 0) s_rank = atomicAdd(&g_done, 1u);
    __syncthreads();
    if (s_rank == GRID_C - 1) {
        float sum = 0.f;
        for (int b = tid; b < B_ROWS; b += 256) {
            float t = g_tgt[b];
            float tc = fminf(fmaxf(t, -1.0f + EPS_A), 1.0f - EPS_A);
            float num = S_SCALE * cosf(acosf(tc) + M_MARG);
            float excl = g_rowsum[b] - expf(S_SCALE * t);
            float denom = expf(num) + excl;
            sum += num - logf(denom);
        }
        #pragma unroll
        for (int o = 16; o > 0; o >>= 1) sum += __shfl_xor_sync(0xffffffffu, sum, o);
        __shared__ float lred[8];
        if (lane == 0) lred[warp] = sum;
        __syncthreads();
        if (warp == 0) {
            float v = (lane < 8) ? lred[lane] : 0.f;
            #pragma unroll
            for (int o = 4; o > 0; o >>= 1) v += __shfl_xor_sync(0xffffffffu, v, o);
            if (lane == 0) out[0] = -v / (float)B_ROWS;
        }
    }
}

// ---------------- launch ----------------
extern "C" void kernel_launch(void* const* d_in, const int* in_sizes, int n_in,
                              void* d_out, int out_size) {
    const float* features = (const float*)d_in[0];
    const float* W        = (const float*)d_in[1];
    const void*  y_true   = d_in[2];
    float* out = (float*)d_out;

    cudaFuncSetAttribute(gemm_exp_kernel,
                         cudaFuncAttributeMaxDynamicSharedMemorySize, SMEM_BYTES);

    norm_tgt_kernel<<<B_ROWS, 128>>>(features, W, y_true);
    gemm_exp_kernel<<<GRID_C, 256, SMEM_BYTES>>>(W, out);
}

// round 17
// speedup vs baseline: 1.2400x; 1.0310x over previous
#include <cuda_runtime.h>
#include <cuda_bf16.h>
#include <cstdint>

// ---------------- problem constants ----------------
#define B_ROWS 1024
#define D_DIM  512
#define C_CLS  100000
#define S_SCALE 64.0f
#define M_MARG  0.5f
#define EPS_A   1e-07f

// fp8 quantization scales: logits come out multiplied by SX*SW = 1024
#define SX 16.0f
#define SW 64.0f
#define INV_SXSW (S_SCALE / (SX * SW))                 // 0.0625
#define EXP2K (INV_SXSW * 1.4426950408889634f)         // ex2(acc*EXP2K)

// GEMM tiling: per-CTA 128 rows x 128 classes, K chunked by 128 fp8 elems
#define BM 128
#define BN 128
#define BK 128
#define ROW_BYTES   144                        // 128 fp8 = 128B data + 16B pad
#define TILE_BYTES  (128 * ROW_BYTES)          // 18432
#define STAGE_BYTES (2 * TILE_BYTES)           // X + W
#define SMEM_BYTES  (2 * STAGE_BYTES + 256)

// ---------------- scratch ----------------
__device__ float    g_xn[B_ROWS * D_DIM];          // normalized features fp32
__device__ uint8_t  g_x8[B_ROWS * D_DIM];          // normalized features e4m3 (x SX)
__device__ uint8_t  g_w8[(size_t)C_CLS * D_DIM];   // W e4m3 (x SW), written by gemm prologue
__device__ float    g_rowsum[B_ROWS];
__device__ float    g_tgt[B_ROWS];

// ---------------- helpers ----------------
__device__ __forceinline__ void ldsm_x4(unsigned r[4], unsigned addr) {
    asm volatile("ldmatrix.sync.aligned.m8n8.x4.shared.b16 {%0,%1,%2,%3}, [%4];"
                 : "=r"(r[0]), "=r"(r[1]), "=r"(r[2]), "=r"(r[3]) : "r"(addr));
}

__device__ __forceinline__ void mma_fp8(float c[4], const unsigned a[4], const unsigned b[2]) {
    asm volatile(
        "mma.sync.aligned.m16n8k32.row.col.f32.e4m3.e4m3.f32 "
        "{%0,%1,%2,%3},{%4,%5,%6,%7},{%8,%9},{%0,%1,%2,%3};"
        : "+f"(c[0]), "+f"(c[1]), "+f"(c[2]), "+f"(c[3])
        : "r"(a[0]), "r"(a[1]), "r"(a[2]), "r"(a[3]),
          "r"(b[0]), "r"(b[1]));
}

__device__ __forceinline__ float ex2f(float x) {
    float y;
    asm("ex2.approx.ftz.f32 %0, %1;" : "=f"(y) : "f"(x));
    return y;
}

// pack 4 floats -> 4 e4m3 bytes (byte i = element i)
__device__ __forceinline__ unsigned pack_e4m3x4(float x0, float x1, float x2, float x3) {
    unsigned short lo, hi;
    asm("cvt.rn.satfinite.e4m3x2.f32 %0, %1, %2;" : "=h"(lo) : "f"(x1), "f"(x0));
    asm("cvt.rn.satfinite.e4m3x2.f32 %0, %1, %2;" : "=h"(hi) : "f"(x3), "f"(x2));
    return (unsigned)lo | ((unsigned)hi << 16);
}

__device__ __forceinline__ void cp16(unsigned dst, const void* src, bool valid) {
    int sz = valid ? 16 : 0;
    asm volatile("cp.async.cg.shared.global [%0], [%1], 16, %2;\n"
                 :: "r"(dst), "l"(src), "r"(sz));
}
__device__ __forceinline__ void cp_commit() {
    asm volatile("cp.async.commit_group;\n" ::: "memory");
}
__device__ __forceinline__ void cp_wait0() {
    asm volatile("cp.async.wait_group 0;\n" ::: "memory");
}

// ---------------- kernel 1: L2-normalize + quantize + fp32 true-class logit ----------------
// Inline y-dtype detection (16 cached loads, uniform branch) — no detect kernel.
__global__ __launch_bounds__(128) void norm_tgt_kernel(const float* __restrict__ X,
                                                       const float* __restrict__ W,
                                                       const void* __restrict__ y) {
    int b = blockIdx.x;
    const float* xr = X + (size_t)b * D_DIM;
    float s = 0.f;
    #pragma unroll
    for (int i = threadIdx.x; i < D_DIM; i += 128) {
        float v = xr[i];
        s += v * v;
    }
    #pragma unroll
    for (int o = 16; o > 0; o >>= 1) s += __shfl_xor_sync(0xffffffffu, s, o);
    __shared__ float red[4];
    int w = threadIdx.x >> 5;
    if ((threadIdx.x & 31) == 0) red[w] = s;
    __syncthreads();
    float tot = red[0] + red[1] + red[2] + red[3];
    float inv = 1.0f / fmaxf(sqrtf(tot), 1e-12f);

    int j = threadIdx.x * 4;
    float4 v = *(const float4*)(xr + j);
    v.x *= inv; v.y *= inv; v.z *= inv; v.w *= inv;
    *(float4*)(g_xn + (size_t)b * D_DIM + j) = v;
    unsigned p = pack_e4m3x4(v.x * SX, v.y * SX, v.z * SX, v.w * SX);
    *(unsigned*)(g_x8 + (size_t)b * D_DIM + j) = p;

    // inline y dtype detection: int64 values < 2^31 -> all odd 32-bit words zero
    const int* y32 = (const int*)y;
    int is64 = 1;
    #pragma unroll
    for (int i = 0; i < 16; i++)
        if (y32[2 * i + 1] != 0) is64 = 0;

    long long c;
    if (is64) c = ((const long long*)y)[b];
    else      c = (long long)y32[b];
    if (c < 0) c = 0;
    if (c >= C_CLS) c = C_CLS - 1;
    float4 wv = *(const float4*)(W + (size_t)c * D_DIM + j);
    float t = v.x * wv.x + v.y * wv.y + v.z * wv.z + v.w * wv.w;
    #pragma unroll
    for (int o = 16; o > 0; o >>= 1) t += __shfl_xor_sync(0xffffffffu, t, o);
    __syncthreads();
    if ((threadIdx.x & 31) == 0) red[w] = t;
    __syncthreads();
    if (threadIdx.x == 0) {
        g_tgt[b] = red[0] + red[1] + red[2] + red[3];
        g_rowsum[b] = 0.f;
    }
}

// ---------------- kernel 2: fused W-quantize + fp8 GEMM + exp + row-sum ----------------
// R13 verbatim: 256 threads, 8 warps (2M x 4N, per-warp 64x32), 2-stage cp.async,
// occ=2, A-fragment double buffer. No fused tail (threadfence convoy costs more).
__global__ __launch_bounds__(256, 2) void gemm_exp_kernel(const float* __restrict__ W) {
    extern __shared__ char sm_raw[];

    const int tid  = threadIdx.x;
    const int lane = tid & 31;
    const int warp = tid >> 5;
    const int warpM = warp & 1;    // 2 warps over M (64 rows each)
    const int warpN = warp >> 1;   // 4 warps over N (32 cols each)
    const int colbase = blockIdx.x * BN;
    const bool full_tile = (colbase + BN <= C_CLS);

    // ---- prologue: quantize this CTA's W stripe to e4m3 (x SW) ----
    {
        const size_t base = (size_t)colbase * D_DIM;
        const int vrows = full_tile ? BN : (C_CLS - colbase);
        const size_t velems = (size_t)vrows * D_DIM;
        for (size_t i = (size_t)tid * 4; i < velems; i += 256 * 4) {
            float4 v = *(const float4*)(W + base + i);
            unsigned p = pack_e4m3x4(v.x * SW, v.y * SW, v.z * SW, v.w * SW);
            *(unsigned*)(g_w8 + base + i) = p;
        }
        __syncthreads();
    }

    unsigned sbase = (unsigned)__cvta_generic_to_shared(sm_raw);
    sbase = (sbase + 255u) & ~255u;

    const int lr  = tid >> 3;      // load row 0..31
    const int seg = tid & 7;       // 16B segment (8 per 128B row)

    bool wvalid[4];
    const uint8_t* wrow[4];
    #pragma unroll
    for (int i = 0; i < 4; i++) {
        int c = colbase + lr + 32 * i;
        wvalid[i] = (c < C_CLS);
        wrow[i] = g_w8 + (size_t)(wvalid[i] ? c : colbase) * D_DIM + seg * 16;
    }

    unsigned st_off[4];
    #pragma unroll
    for (int i = 0; i < 4; i++)
        st_off[i] = (unsigned)((lr + 32 * i) * ROW_BYTES + seg * 16);

    auto load_chunk = [&](int rt, int kt, int st) {
        const unsigned xs = sbase + (unsigned)st * (unsigned)STAGE_BYTES;
        const unsigned ws = xs + (unsigned)TILE_BYTES;
        const uint8_t* xb = g_x8 + (size_t)(rt * BM) * D_DIM + kt * BK + seg * 16;
        #pragma unroll
        for (int i = 0; i < 4; i++) {
            cp16(xs + st_off[i], xb + (size_t)(lr + 32 * i) * D_DIM, true);
            cp16(ws + st_off[i], wrow[i] + kt * BK, wvalid[i]);
        }
    };

    const int lrow = lane & 15;
    const int lhi  = (lane >> 4) * 16;
    const int qrow = lane >> 2;
    const int qcol = lane & 3;

    unsigned a_off[4], b_off[2];
    #pragma unroll
    for (int mi = 0; mi < 4; mi++)
        a_off[mi] = (unsigned)((warpM * 64 + mi * 16 + lrow) * ROW_BYTES + lhi);
    #pragma unroll
    for (int p = 0; p < 2; p++)
        b_off[p] = (unsigned)((warpN * 32 + p * 16 + lrow) * ROW_BYTES + lhi) + (unsigned)TILE_BYTES;

    load_chunk(0, 0, 0);
    cp_commit();

    float acc[4][4][4];
    #pragma unroll
    for (int mi = 0; mi < 4; mi++)
        #pragma unroll
        for (int ni = 0; ni < 4; ni++)
            #pragma unroll
            for (int r = 0; r < 4; r++) acc[mi][ni][r] = 0.f;

    for (int rt = 0; rt < 8; rt++) {
        #pragma unroll
        for (int kt = 0; kt < 4; kt++) {
            const int s = kt & 1;

            cp_wait0();
            __syncthreads();

            // prefetch next chunk
            if (kt < 3) {
                load_chunk(rt, kt + 1, s ^ 1);
                cp_commit();
            } else if (rt < 7) {
                load_chunk(rt + 1, 0, s ^ 1);
                cp_commit();
            }

            const unsigned stg = sbase + (unsigned)(s * STAGE_BYTES);

            // A-fragment double buffer across k-steps (B loaded per k-step, first)
            unsigned a[2][4][4];
            #pragma unroll
            for (int mi = 0; mi < 4; mi++)
                ldsm_x4(a[0][mi], stg + a_off[mi]);   // preload A for ks=0

            #pragma unroll
            for (int ks = 0; ks < 4; ks++) {
                const int cur = ks & 1;
                const int nxt = cur ^ 1;
                const unsigned kb = stg + (unsigned)(ks * 32);

                unsigned bq[2][4];
                #pragma unroll
                for (int p = 0; p < 2; p++)
                    ldsm_x4(bq[p], kb + b_off[p]);

                if (ks < 3) {
                    const unsigned kb2 = stg + (unsigned)((ks + 1) * 32);
                    #pragma unroll
                    for (int mi = 0; mi < 4; mi++)
                        ldsm_x4(a[nxt][mi], kb2 + a_off[mi]);
                }

                #pragma unroll
                for (int mi = 0; mi < 4; mi++) {
                    #pragma unroll
                    for (int p = 0; p < 2; p++) {
                        unsigned b0[2] = { bq[p][0], bq[p][2] };
                        unsigned b1[2] = { bq[p][1], bq[p][3] };
                        mma_fp8(acc[mi][2 * p + 0], a[cur][mi], b0);
                        mma_fp8(acc[mi][2 * p + 1], a[cur][mi], b1);
                    }
                }
            }
        }

        // epilogue for this row-tile
        if (full_tile) {
            #pragma unroll
            for (int mi = 0; mi < 4; mi++) {
                int r0 = rt * BM + warpM * 64 + mi * 16 + qrow;
                int r1 = r0 + 8;
                float s0 = 0.f, s1 = 0.f;
                #pragma unroll
                for (int ni = 0; ni < 4; ni++) {
                    s0 += ex2f(EXP2K * acc[mi][ni][0]);
                    s0 += ex2f(EXP2K * acc[mi][ni][1]);
                    s1 += ex2f(EXP2K * acc[mi][ni][2]);
                    s1 += ex2f(EXP2K * acc[mi][ni][3]);
                    #pragma unroll
                    for (int r = 0; r < 4; r++) acc[mi][ni][r] = 0.f;
                }
                s0 += __shfl_xor_sync(0xffffffffu, s0, 1);
                s0 += __shfl_xor_sync(0xffffffffu, s0, 2);
                s1 += __shfl_xor_sync(0xffffffffu, s1, 1);
                s1 += __shfl_xor_sync(0xffffffffu, s1, 2);
                if (qcol == 0) {
                    atomicAdd(g_rowsum + r0, s0);
                    atomicAdd(g_rowsum + r1, s1);
                }
            }
        } else {
            #pragma unroll
            for (int mi = 0; mi < 4; mi++) {
                int r0 = rt * BM + warpM * 64 + mi * 16 + qrow;
                int r1 = r0 + 8;
                float s0 = 0.f, s1 = 0.f;
                #pragma unroll
                for (int ni = 0; ni < 4; ni++) {
                    int c0 = colbase + warpN * 32 + ni * 8 + 2 * qcol;
                    int c1 = c0 + 1;
                    if (c0 < C_CLS) {
                        s0 += ex2f(EXP2K * acc[mi][ni][0]);
                        s1 += ex2f(EXP2K * acc[mi][ni][2]);
                    }
                    if (c1 < C_CLS) {
                        s0 += ex2f(EXP2K * acc[mi][ni][1]);
                        s1 += ex2f(EXP2K * acc[mi][ni][3]);
                    }
                    #pragma unroll
                    for (int r = 0; r < 4; r++) acc[mi][ni][r] = 0.f;
                }
                s0 += __shfl_xor_sync(0xffffffffu, s0, 1);
                s0 += __shfl_xor_sync(0xffffffffu, s0, 2);
                s1 += __shfl_xor_sync(0xffffffffu, s1, 1);
                s1 += __shfl_xor_sync(0xffffffffu, s1, 2);
                if (qcol == 0) {
                    atomicAdd(g_rowsum + r0, s0);
                    atomicAdd(g_rowsum + r1, s1);
                }
            }
        }
    }
}

// ---------------- kernel 3: per-row loss + mean ----------------
__global__ __launch_bounds__(1024) void loss_kernel(float* __restrict__ out) {
    int b = threadIdx.x;
    float t = g_tgt[b];
    float tc = fminf(fmaxf(t, -1.0f + EPS_A), 1.0f - EPS_A);
    float num = S_SCALE * cosf(acosf(tc) + M_MARG);
    float excl = g_rowsum[b] - expf(S_SCALE * t);
    float denom = expf(num) + excl;
    float L = num - logf(denom);

    #pragma unroll
    for (int o = 16; o > 0; o >>= 1) L += __shfl_xor_sync(0xffffffffu, L, o);
    __shared__ float red[32];
    int w = threadIdx.x >> 5;
    if ((threadIdx.x & 31) == 0) red[w] = L;
    __syncthreads();
    if (w == 0) {
        float v = red[threadIdx.x & 31];
        #pragma unroll
        for (int o = 16; o > 0; o >>= 1) v += __shfl_xor_sync(0xffffffffu, v, o);
        if (threadIdx.x == 0) out[0] = -v / (float)B_ROWS;
    }
}

// ---------------- launch ----------------
extern "C" void kernel_launch(void* const* d_in, const int* in_sizes, int n_in,
                              void* d_out, int out_size) {
    const float* features = (const float*)d_in[0];
    const float* W        = (const float*)d_in[1];
    const void*  y_true   = d_in[2];
    float* out = (float*)d_out;

    cudaFuncSetAttribute(gemm_exp_kernel,
                         cudaFuncAttributeMaxDynamicSharedMemorySize, SMEM_BYTES);

    norm_tgt_kernel<<<B_ROWS, 128>>>(features, W, y_true);
    const int grid = (C_CLS + BN - 1) / BN;  // 782
    gemm_exp_kernel<<<grid, 256, SMEM_BYTES>>>(W);
    loss_kernel<<<1, 1024>>>(out);
}